// round 1
// baseline (speedup 1.0000x reference)
#include <cuda_runtime.h>
#include <math_constants.h>
#include <stdint.h>

#define CCH 256               // channels
#define NLEV 4

// Per-level spatial sizes and offsets into the transposed scratch (in floats).
// HW*C: 65536*256, 16384*256, 4096*256, 1024*256
__device__ __align__(16) float g_featT[22282240];   // ~85M floats = 89.1 MB scratch

// ---------------------------------------------------------------------------
// Transpose (C, HW) -> (HW, C) for one pyramid level, smem-tiled, coalesced
// both directions. Writes into g_featT at out_off.
// ---------------------------------------------------------------------------
__global__ void transpose_chw_to_hwc(const float* __restrict__ in,
                                     size_t out_off, int HW) {
    __shared__ float tile[32][33];
    const int tx = threadIdx.x;          // 0..31
    const int ty = threadIdx.y;          // 0..7
    const int x  = blockIdx.x * 32 + tx; // HW index (read phase)
    const int c0 = blockIdx.y * 32;      // channel tile base

#pragma unroll
    for (int j = 0; j < 32; j += 8) {
        tile[ty + j][tx] = in[(size_t)(c0 + ty + j) * HW + x];
    }
    __syncthreads();

    const int xo = blockIdx.x * 32 + ty; // HW index (write phase)
#pragma unroll
    for (int j = 0; j < 32; j += 8) {
        g_featT[out_off + (size_t)(xo + j) * CCH + (c0 + tx)] = tile[tx][ty + j];
    }
}

// ---------------------------------------------------------------------------
// ROIAlign main kernel. One block per proposal; 256 threads =
// 64 channel-groups (float4) x 4 output-pixel slices.
// Reads transposed features (HW, C): warp loads 512B contiguous per corner.
// ---------------------------------------------------------------------------
__global__ __launch_bounds__(256) void roialign_kernel(
    const float* __restrict__ proposals,
    float* __restrict__ out) {

    const int n   = blockIdx.x;
    const int tid = threadIdx.x;
    const int g   = tid & 63;   // channel group -> channels 4g..4g+3
    const int p   = tid >> 6;   // pixel slice 0..3

    __shared__ int   s_x0[14], s_x1[14], s_y0[14], s_y1[14];
    __shared__ float s_dx0[14], s_dx1[14], s_dy0[14], s_dy1[14];

    // --- per-proposal setup (computed redundantly; uniform across block) ---
    const float px1 = proposals[n * 4 + 0];
    const float py1 = proposals[n * 4 + 1];
    const float px2 = proposals[n * 4 + 2];
    const float py2 = proposals[n * 4 + 3];

    const float pw = px2 - px1;
    const float ph = py2 - py1;
    const float lf = floorf(2.0f + log2f(sqrtf(pw * ph) / 224.0f));
    int lvl = (int)lf;
    lvl = lvl < 0 ? 0 : (lvl > 3 ? 3 : lvl);

    const float scales[NLEV] = {0.25f, 0.125f, 0.0625f, 0.03125f};
    const int   sizes [NLEV] = {256, 128, 64, 32};
    const size_t offs [NLEV] = {0, 16777216, 16777216 + 4194304,
                                16777216 + 4194304 + 1048576};

    const float sc  = scales[lvl];
    const int   Sz  = sizes[lvl];
    const float bx1 = px1 * sc, by1 = py1 * sc;
    const float bx2 = px2 * sc, by2 = py2 * sc;
    const float w_unit = ((bx2 - bx1) / 7.0f) * 0.5f;
    const float h_unit = ((by2 - by1) / 7.0f) * 0.5f;

    if (tid < 14) {
        const float fi = (float)tid + 0.5f;
        // x axis
        {
            const float x  = bx1 + fi * w_unit;
            const int   xf = (int)floorf(x);
            int x0 = xf;     x0 = x0 < 0 ? 0 : (x0 > Sz - 1 ? Sz - 1 : x0);
            int x1 = xf + 1; x1 = x1 < 0 ? 0 : (x1 > Sz - 1 ? Sz - 1 : x1);
            s_x0[tid]  = x0;
            s_x1[tid]  = x1;
            s_dx0[tid] = x - (float)x0;   // (x - x0f)
            s_dx1[tid] = (float)x1 - x;   // (x1f - x)
        }
        // y axis
        {
            const float y  = by1 + fi * h_unit;
            const int   yf = (int)floorf(y);
            int y0 = yf;     y0 = y0 < 0 ? 0 : (y0 > Sz - 1 ? Sz - 1 : y0);
            int y1 = yf + 1; y1 = y1 < 0 ? 0 : (y1 > Sz - 1 ? Sz - 1 : y1);
            s_y0[tid]  = y0;
            s_y1[tid]  = y1;
            s_dy0[tid] = y - (float)y0;
            s_dy1[tid] = (float)y1 - y;
        }
    }
    __syncthreads();

    const float* __restrict__ fbase = g_featT + offs[lvl];
    const int cb = g * 4;

    for (int pix = p; pix < 49; pix += 4) {
        const int oy = pix / 7;
        const int ox = pix - oy * 7;

        float4 vmax = make_float4(-CUDART_INF_F, -CUDART_INF_F,
                                  -CUDART_INF_F, -CUDART_INF_F);
#pragma unroll
        for (int sy = 0; sy < 2; ++sy) {
            const int   gy  = oy * 2 + sy;
            const int   y0  = s_y0[gy], y1 = s_y1[gy];
            const float dy0 = s_dy0[gy], dy1 = s_dy1[gy];
#pragma unroll
            for (int sx = 0; sx < 2; ++sx) {
                const int   gx  = ox * 2 + sx;
                const int   x0  = s_x0[gx], x1 = s_x1[gx];
                const float dx0 = s_dx0[gx], dx1 = s_dx1[gx];

                const float wa = dx1 * dy1;
                const float wb = dx1 * dy0;
                const float wc = dx0 * dy1;
                const float wd = dx0 * dy0;

                const float4 la = *reinterpret_cast<const float4*>(
                    fbase + ((size_t)y0 * Sz + x0) * CCH + cb);
                const float4 lb = *reinterpret_cast<const float4*>(
                    fbase + ((size_t)y1 * Sz + x0) * CCH + cb);
                const float4 lc = *reinterpret_cast<const float4*>(
                    fbase + ((size_t)y0 * Sz + x1) * CCH + cb);
                const float4 ld = *reinterpret_cast<const float4*>(
                    fbase + ((size_t)y1 * Sz + x1) * CCH + cb);

                float4 v;
                v.x = wa * la.x + wb * lb.x + wc * lc.x + wd * ld.x;
                v.y = wa * la.y + wb * lb.y + wc * lc.y + wd * ld.y;
                v.z = wa * la.z + wb * lb.z + wc * lc.z + wd * ld.z;
                v.w = wa * la.w + wb * lb.w + wc * lc.w + wd * ld.w;

                vmax.x = fmaxf(vmax.x, v.x);
                vmax.y = fmaxf(vmax.y, v.y);
                vmax.z = fmaxf(vmax.z, v.z);
                vmax.w = fmaxf(vmax.w, v.w);
            }
        }

        // out shape (N, C, 7, 7): idx = ((n*C + c)*49 + pix)
        const size_t ob = ((size_t)n * CCH + cb) * 49 + pix;
        out[ob          ] = vmax.x;
        out[ob + 49     ] = vmax.y;
        out[ob + 98     ] = vmax.z;
        out[ob + 147    ] = vmax.w;
    }
}

// ---------------------------------------------------------------------------
// Launch: 4 transposes (one per level) + the ROIAlign kernel.
// All on the default stream; graph-capturable, allocation-free.
// ---------------------------------------------------------------------------
extern "C" void kernel_launch(void* const* d_in, const int* in_sizes, int n_in,
                              void* d_out, int out_size) {
    const float* feats[NLEV] = {
        (const float*)d_in[0],  // p2: (1,256,256,256)
        (const float*)d_in[1],  // p3: (1,256,128,128)
        (const float*)d_in[2],  // p4: (1,256,64,64)
        (const float*)d_in[3],  // p5: (1,256,32,32)
    };
    const float* proposals = (const float*)d_in[4];
    const int N = in_sizes[4] / 4;

    const int    HWs [NLEV] = {65536, 16384, 4096, 1024};
    const size_t offs[NLEV] = {0, 16777216, 16777216 + 4194304,
                               16777216 + 4194304 + 1048576};

    dim3 tb(32, 8);
    for (int l = 0; l < NLEV; ++l) {
        dim3 grid(HWs[l] / 32, CCH / 32);
        transpose_chw_to_hwc<<<grid, tb>>>(feats[l], offs[l], HWs[l]);
    }

    roialign_kernel<<<N, 256>>>(proposals, (float*)d_out);
}